// round 2
// baseline (speedup 1.0000x reference)
#include <cuda_runtime.h>

#define N_ATOMS 50000
#define N_BONDS 100000
#define MAX_NB  6
#define F_ATOM  133
#define F_BOND  147
#define HID     600

// Scratch (allocation-free: device globals, zero-init bss)
static __device__ float g_inp [(size_t)N_BONDS * HID];
static __device__ float g_msg0[(size_t)N_BONDS * HID];
static __device__ float g_msg1[(size_t)N_BONDS * HID];
static __device__ float g_amsg[(size_t)N_ATOMS * HID];

constexpr int BM = 128, BN = 128, BK = 8, TM = 8, TN = 8;
constexpr int NT = (BM / TM) * (BN / TN);  // 256 threads

// MODE 0: plain A [M,K] row-major (init: A=f_bonds)
// MODE 1: A row b = g_amsg[b2a[b]] - msg_old[b2revb[b]]  (K = HID)
// MODE 2: A row a = concat(f_atoms[a], g_amsg[a])        (K = F_ATOM+HID)
// EPI  0: g_inp = C ; g_msg0 = relu(C)
// EPI  1: msg_new = relu(g_inp + C)
// EPI  2: Cout = relu(C + bias)
template <int MODE, int EPI>
__global__ __launch_bounds__(NT)
void gemm_kernel(const float* __restrict__ A,
                 const int* __restrict__ gi1,
                 const int* __restrict__ gi2,
                 const float* __restrict__ B,
                 const float* __restrict__ bias,
                 float* __restrict__ Cout,
                 int M, int K, int srcIsMsg0)
{
    // __align__(16): we do 128-bit LDS/STS into these; language only
    // guarantees 4B alignment for float arrays.
    __shared__ __align__(16) float As[2][BK][BM];
    __shared__ __align__(16) float Bs[2][BK][BN];

    const int tid = threadIdx.x;
    const int n0 = blockIdx.x * BN;   // n-tile major -> A-panel L2 reuse
    const int m0 = blockIdx.y * BM;

    // ---- A loader setup: thread loads 4 scalars of one A row ----
    const int arow = tid >> 1;
    const int ak0  = (tid & 1) * 4;
    const int grow = m0 + arow;
    const bool rowok = grow < M;
    const float* pa0 = nullptr;
    const float* pa1 = nullptr;
    if (MODE == 0) {
        pa0 = A + (size_t)(rowok ? grow : 0) * K;
    } else if (MODE == 1) {
        const float* msg_old = srcIsMsg0 ? g_msg0 : g_msg1;
        const int ia = rowok ? gi1[grow] : 0;
        const int ib = rowok ? gi2[grow] : 0;
        pa0 = g_amsg  + (size_t)ia * HID;
        pa1 = msg_old + (size_t)ib * HID;
    } else {
        pa0 = A      + (size_t)(rowok ? grow : 0) * F_ATOM;
        pa1 = g_amsg + (size_t)(rowok ? grow : 0) * HID;
    }

    // ---- B loader setup: thread loads one float4 of W ----
    const int bk = tid >> 5;          // 0..7
    const int bn = (tid & 31) * 4;    // 0..124
    const bool bok = (n0 + bn) < HID; // HID % 4 == 0 -> vector-granular guard

    const int numK = (K + BK - 1) / BK;

    float ra[4], rb[4];
    float acc[TM][TN];
    #pragma unroll
    for (int i = 0; i < TM; i++)
        #pragma unroll
        for (int j = 0; j < TN; j++) acc[i][j] = 0.f;

    const int tx = tid & 15, ty = tid >> 4;
    const int rbase = ty * TM, cbase = tx * TN;

    auto loadG = [&](int kt) {
        const int kb = kt * BK;
        #pragma unroll
        for (int i = 0; i < 4; i++) {
            const int k = kb + ak0 + i;
            float v = 0.f;
            if (rowok) {
                if (MODE == 0)      v = (k < K) ? pa0[k] : 0.f;
                else if (MODE == 1) v = pa0[k] - pa1[k];      // K=600 exact, always in range
                else                v = (k >= K) ? 0.f
                                        : (k < F_ATOM ? pa0[k] : pa1[k - F_ATOM]);
            }
            ra[i] = v;
        }
        const int gk = kb + bk;
        if (gk < K && bok) {
            const float4 v = *(const float4*)(B + (size_t)gk * HID + (n0 + bn));
            rb[0] = v.x; rb[1] = v.y; rb[2] = v.z; rb[3] = v.w;
        } else {
            rb[0] = rb[1] = rb[2] = rb[3] = 0.f;
        }
    };
    auto storeS = [&](int buf) {
        #pragma unroll
        for (int i = 0; i < 4; i++) As[buf][ak0 + i][arow] = ra[i];
        *(float4*)&Bs[buf][bk][bn] = make_float4(rb[0], rb[1], rb[2], rb[3]);
    };

    loadG(0);
    storeS(0);
    __syncthreads();

    for (int kt = 0; kt < numK; kt++) {
        const int cur = kt & 1;
        const bool more = (kt + 1) < numK;
        if (more) loadG(kt + 1);   // LDG latency hidden behind compute

        #pragma unroll
        for (int k = 0; k < BK; k++) {
            float fa[TM], fb[TN];
            const float4 a0 = *(const float4*)&As[cur][k][rbase];
            const float4 a1 = *(const float4*)&As[cur][k][rbase + 4];
            fa[0] = a0.x; fa[1] = a0.y; fa[2] = a0.z; fa[3] = a0.w;
            fa[4] = a1.x; fa[5] = a1.y; fa[6] = a1.z; fa[7] = a1.w;
            const float4 b0 = *(const float4*)&Bs[cur][k][cbase];
            const float4 b1 = *(const float4*)&Bs[cur][k][cbase + 4];
            fb[0] = b0.x; fb[1] = b0.y; fb[2] = b0.z; fb[3] = b0.w;
            fb[4] = b1.x; fb[5] = b1.y; fb[6] = b1.z; fb[7] = b1.w;
            #pragma unroll
            for (int i = 0; i < TM; i++)
                #pragma unroll
                for (int j = 0; j < TN; j++)
                    acc[i][j] = fmaf(fa[i], fb[j], acc[i][j]);
        }
        if (more) storeS(cur ^ 1);
        __syncthreads();
    }

    // ---- fused epilogue ----
    float* msg_new = nullptr;
    if (EPI == 1) msg_new = srcIsMsg0 ? g_msg1 : g_msg0;
    #pragma unroll
    for (int i = 0; i < TM; i++) {
        const int r = m0 + rbase + i;
        if (r >= M) break;
        const size_t ro = (size_t)r * HID;
        #pragma unroll
        for (int j = 0; j < TN; j++) {
            const int c = n0 + cbase + j;
            if (c >= HID) continue;
            const float v = acc[i][j];
            if (EPI == 0) {
                g_inp [ro + c] = v;
                g_msg0[ro + c] = fmaxf(v, 0.f);
            } else if (EPI == 1) {
                msg_new[ro + c] = fmaxf(g_inp[ro + c] + v, 0.f);
            } else {
                Cout[ro + c] = fmaxf(v + bias[c], 0.f);
            }
        }
    }
}

// a_message[a] = sum_j message[a2b[a][j]]   (one block per atom, float4 rows)
__global__ __launch_bounds__(128)
void aggregate_kernel(const int* __restrict__ a2b, int srcIsMsg0)
{
    const float* __restrict__ msg = srcIsMsg0 ? g_msg0 : g_msg1;
    const int a = blockIdx.x;
    const int* row = a2b + (size_t)a * MAX_NB;
    const float4* p[MAX_NB];
    #pragma unroll
    for (int j = 0; j < MAX_NB; j++)
        p[j] = (const float4*)(msg + (size_t)row[j] * HID);
    float4* outp = (float4*)(g_amsg + (size_t)a * HID);
    for (int h = threadIdx.x; h < HID / 4; h += blockDim.x) {
        float4 s = p[0][h];
        #pragma unroll
        for (int j = 1; j < MAX_NB; j++) {
            const float4 v = p[j][h];
            s.x += v.x; s.y += v.y; s.z += v.z; s.w += v.w;
        }
        outp[h] = s;
    }
}

extern "C" void kernel_launch(void* const* d_in, const int* in_sizes, int n_in,
                              void* d_out, int out_size)
{
    const float* f_atoms = (const float*)d_in[0];
    const float* f_bonds = (const float*)d_in[1];
    const int*   a2b     = (const int*)  d_in[2];
    const int*   b2a     = (const int*)  d_in[3];
    const int*   b2revb  = (const int*)  d_in[4];
    const float* W_i     = (const float*)d_in[5];
    const float* W_h     = (const float*)d_in[6];
    const float* W_o     = (const float*)d_in[7];
    const float* b_o     = (const float*)d_in[8];
    float* out = (float*)d_out;

    const dim3 blk(NT);
    const dim3 grid_b((HID + BN - 1) / BN, (N_BONDS + BM - 1) / BM); // 5 x 782
    const dim3 grid_a((HID + BN - 1) / BN, (N_ATOMS + BM - 1) / BM); // 5 x 391

    // inp = f_bonds @ W_i ; msg0 = relu(inp)
    gemm_kernel<0, 0><<<grid_b, blk>>>(f_bonds, nullptr, nullptr, W_i, nullptr, nullptr,
                                       N_BONDS, F_BOND, 0);

    int src = 1;  // message currently in g_msg0
    for (int it = 0; it < 5; it++) {   // DEPTH-1 iterations
        aggregate_kernel<<<N_ATOMS, 128>>>(a2b, src);
        gemm_kernel<1, 1><<<grid_b, blk>>>(nullptr, b2a, b2revb, W_h, nullptr, nullptr,
                                           N_BONDS, HID, src);
        src ^= 1;
    }

    aggregate_kernel<<<N_ATOMS, 128>>>(a2b, src);  // final message after 5 iters
    gemm_kernel<2, 2><<<grid_a, blk>>>(f_atoms, nullptr, nullptr, W_o, b_o, out,
                                       N_ATOMS, F_ATOM + HID, 0);
}

// round 3
// speedup vs baseline: 2.0992x; 2.0992x over previous
#include <cuda_runtime.h>
#include <cuda_bf16.h>
#include <stdint.h>

#define N_ATOMS 50000
#define N_BONDS 100000
#define MAX_NB  6
#define F_ATOM  133
#define F_BOND  147
#define HID     600

// k-chunks of 16 base-k per GEMM
constexpr int NC_I = 10;   // ceil(147/16)
constexpr int NC_H = 38;   // ceil(600/16)
constexpr int NC_O = 46;   // ceil(733/16)

// Scratch (allocation-free device globals). +16 float tail pad for vector loads.
static __device__ float g_inp [(size_t)N_BONDS * HID + 16];
static __device__ float g_msg0[(size_t)N_BONDS * HID + 16];
static __device__ float g_msg1[(size_t)N_BONDS * HID + 16];
static __device__ float g_amsg[(size_t)N_ATOMS * HID + 16];

// Pre-split weights, n-major pair-packed: [n][chunk][16 u32]
// words 0..7 = hi bf16 pairs (k = 2w, 2w+1), words 8..15 = mid pairs.
static __device__ __align__(16) uint32_t g_Wi2[(size_t)HID * NC_I * 16];
static __device__ __align__(16) uint32_t g_Wh2[(size_t)HID * NC_H * 16];
static __device__ __align__(16) uint32_t g_Wo2[(size_t)HID * NC_O * 16];

__device__ __forceinline__ void split2(float v, uint16_t& h, uint16_t& m) {
    __nv_bfloat16 bh = __float2bfloat16_rn(v);
    float r = v - __bfloat162float(bh);
    __nv_bfloat16 bm = __float2bfloat16_rn(r);
    h = __bfloat16_as_ushort(bh);
    m = __bfloat16_as_ushort(bm);
}

__device__ __forceinline__ void mma16816(float* d, const uint32_t* a, const uint32_t* b) {
    asm volatile(
        "mma.sync.aligned.m16n8k16.row.col.f32.bf16.bf16.f32 "
        "{%0,%1,%2,%3}, {%4,%5,%6,%7}, {%8,%9}, {%0,%1,%2,%3};\n"
        : "+f"(d[0]), "+f"(d[1]), "+f"(d[2]), "+f"(d[3])
        : "r"(a[0]), "r"(a[1]), "r"(a[2]), "r"(a[3]), "r"(b[0]), "r"(b[1]));
}

// ---- weight pre-split: W [K][HID] fp32 -> [n][chunk][16] packed bf16 hi/mid ----
template <int SEL>
__global__ void pack_weights(const float* __restrict__ W)
{
    constexpr int K  = (SEL == 0) ? F_BOND : (SEL == 1) ? HID : (F_ATOM + HID);
    constexpr int NC = (SEL == 0) ? NC_I   : (SEL == 1) ? NC_H : NC_O;
    uint32_t* out = (SEL == 0) ? g_Wi2 : (SEL == 1) ? g_Wh2 : g_Wo2;

    const int idx = blockIdx.x * blockDim.x + threadIdx.x;  // one per (n, chunk)
    if (idx >= HID * NC) return;
    const int n = idx / NC;
    const int c = idx % NC;
    uint32_t w[16];
    #pragma unroll
    for (int i = 0; i < 8; i++) {
        const int k0 = c * 16 + 2 * i;
        const float v0 = (k0     < K) ? W[(size_t)k0       * HID + n] : 0.f;
        const float v1 = (k0 + 1 < K) ? W[(size_t)(k0 + 1) * HID + n] : 0.f;
        uint16_t h0, m0, h1, m1;
        split2(v0, h0, m0); split2(v1, h1, m1);
        w[i]     = (uint32_t)h0 | ((uint32_t)h1 << 16);
        w[8 + i] = (uint32_t)m0 | ((uint32_t)m1 << 16);
    }
    uint32_t* dst = out + (size_t)idx * 16;
    #pragma unroll
    for (int i = 0; i < 16; i++) dst[i] = w[i];
}

// ============================================================================
// bf16x3 tensor-core GEMM, CTA 128x128, 8 warps (2M x 4N), warp tile 64x32.
// MODE 0: A = f_bonds           (K=147)  EPI 0: g_inp=C, g_msg0=relu(C)
// MODE 1: A = amsg[b2a]-msg[b2revb] (K=600) EPI 1: msg_new=relu(g_inp+C)
// MODE 2: A = [f_atoms | amsg]  (K=733)  EPI 2: out=relu(C+bias)
// ============================================================================
template <int MODE, int EPI>
__global__ __launch_bounds__(256)
void gemm_bf16x3(const float* __restrict__ A,
                 const int* __restrict__ gi1, const int* __restrict__ gi2,
                 const float* __restrict__ bias,
                 float* __restrict__ Cout,
                 int M, int srcIsMsg0)
{
    constexpr int K  = (MODE == 0) ? F_BOND : (MODE == 1) ? HID : (F_ATOM + HID);
    constexpr int NC = (MODE == 0) ? NC_I   : (MODE == 1) ? NC_H : NC_O;
    const uint32_t* __restrict__ Bpk =
        (MODE == 0) ? g_Wi2 : (MODE == 1) ? g_Wh2 : g_Wo2;

    // row stride 20 words: 20r mod 32 covers all 8 bank-groups -> conflict-free frag LDS
    __shared__ __align__(16) uint32_t As[2][128][20];
    __shared__ __align__(16) uint32_t Bs[2][128][20];

    const int tid  = threadIdx.x;
    const int n0   = blockIdx.x * 128;
    const int m0   = blockIdx.y * 128;
    const int lane = tid & 31;
    const int warp = tid >> 5;
    const int warpM = warp & 1;
    const int warpN = warp >> 1;
    const int q  = lane & 3;
    const int r8 = lane >> 2;

    // ---- A loader ids: thread -> (row, 8-k segment) ----
    const int  lrow  = tid >> 1;
    const int  lseg  = tid & 1;
    const int  grow  = m0 + lrow;
    const bool rowok = grow < M;

    const float* pa0 = nullptr;
    const float* pa1 = nullptr;
    if (MODE == 0) {
        pa0 = A + (size_t)(rowok ? grow : 0) * F_BOND;
    } else if (MODE == 1) {
        const float* msg_old = srcIsMsg0 ? g_msg0 : g_msg1;
        const int ia = rowok ? gi1[grow] : 0;
        const int ib = rowok ? gi2[grow] : 0;
        pa0 = g_amsg  + (size_t)ia * HID;
        pa1 = msg_old + (size_t)ib * HID;
    } else {
        pa0 = A      + (size_t)(rowok ? grow : 0) * F_ATOM;
        pa1 = g_amsg + (size_t)(rowok ? grow : 0) * HID;
    }

    // ---- B loader ids ----
    const int  brow = tid >> 1;
    const bool bok  = (n0 + brow) < HID;
    const uint32_t* pb = Bpk + (size_t)(bok ? (n0 + brow) : 0) * NC * 16 + lseg * 8;

    uint32_t aw[8];         // 4 hi + 4 mid packed words
    uint4    bt0, bt1;

    auto loadA = [&](int c) {
        const int kb = c * 16 + lseg * 8;
        float v[8];
        if (MODE == 1) {
            if (kb + 8 <= K) {
                const float4 x0 = *(const float4*)(pa0 + kb);
                const float4 x1 = *(const float4*)(pa0 + kb + 4);
                const float4 y0 = *(const float4*)(pa1 + kb);
                const float4 y1 = *(const float4*)(pa1 + kb + 4);
                v[0] = x0.x - y0.x; v[1] = x0.y - y0.y; v[2] = x0.z - y0.z; v[3] = x0.w - y0.w;
                v[4] = x1.x - y1.x; v[5] = x1.y - y1.y; v[6] = x1.z - y1.z; v[7] = x1.w - y1.w;
            } else {
                #pragma unroll
                for (int i = 0; i < 8; i++) { const int k = kb + i; v[i] = (k < K) ? pa0[k] - pa1[k] : 0.f; }
            }
        } else if (MODE == 0) {
            #pragma unroll
            for (int i = 0; i < 8; i++) { const int k = kb + i; v[i] = (rowok && k < K) ? pa0[k] : 0.f; }
        } else {
            #pragma unroll
            for (int i = 0; i < 8; i++) {
                const int k = kb + i;
                float t = 0.f;
                if (rowok && k < K) t = (k < F_ATOM) ? pa0[k] : pa1[k - F_ATOM];
                v[i] = t;
            }
        }
        #pragma unroll
        for (int i = 0; i < 4; i++) {
            uint16_t h0, m0_, h1, m1_;
            split2(v[2 * i],     h0, m0_);
            split2(v[2 * i + 1], h1, m1_);
            aw[i]     = (uint32_t)h0  | ((uint32_t)h1  << 16);
            aw[4 + i] = (uint32_t)m0_ | ((uint32_t)m1_ << 16);
        }
    };
    auto loadB = [&](int c) {
        if (bok) {
            bt0 = *(const uint4*)(pb + (size_t)c * 16);
            bt1 = *(const uint4*)(pb + (size_t)c * 16 + 4);
        } else {
            bt0 = make_uint4(0, 0, 0, 0);
            bt1 = make_uint4(0, 0, 0, 0);
        }
    };
    auto storeS = [&](int buf) {
        *(uint4*)&As[buf][lrow][lseg * 4]     = make_uint4(aw[0], aw[1], aw[2], aw[3]);
        *(uint4*)&As[buf][lrow][8 + lseg * 4] = make_uint4(aw[4], aw[5], aw[6], aw[7]);
        *(uint4*)&Bs[buf][brow][lseg * 8]     = bt0;
        *(uint4*)&Bs[buf][brow][lseg * 8 + 4] = bt1;
    };

    float acc[4][4][4];
    #pragma unroll
    for (int a = 0; a < 4; a++)
        #pragma unroll
        for (int b = 0; b < 4; b++)
            #pragma unroll
            for (int cc = 0; cc < 4; cc++) acc[a][b][cc] = 0.f;

    auto compute = [&](int buf) {
        uint32_t Ah[4][4], Am[4][4];
        #pragma unroll
        for (int mt = 0; mt < 4; mt++) {
            const int rr = warpM * 64 + mt * 16 + r8;
            Ah[mt][0] = As[buf][rr][q];          Ah[mt][1] = As[buf][rr + 8][q];
            Ah[mt][2] = As[buf][rr][q + 4];      Ah[mt][3] = As[buf][rr + 8][q + 4];
            Am[mt][0] = As[buf][rr][q + 8];      Am[mt][1] = As[buf][rr + 8][q + 8];
            Am[mt][2] = As[buf][rr][q + 12];     Am[mt][3] = As[buf][rr + 8][q + 12];
        }
        #pragma unroll
        for (int nt = 0; nt < 4; nt++) {
            const int nn = warpN * 32 + nt * 8 + r8;
            uint32_t Bh[2] = { Bs[buf][nn][q],     Bs[buf][nn][q + 4]  };
            uint32_t Bm[2] = { Bs[buf][nn][q + 8], Bs[buf][nn][q + 12] };
            #pragma unroll
            for (int mt = 0; mt < 4; mt++) {
                mma16816(acc[mt][nt], Ah[mt], Bh);   // hi  * hi
                mma16816(acc[mt][nt], Am[mt], Bh);   // mid * hi
                mma16816(acc[mt][nt], Ah[mt], Bm);   // hi  * mid
            }
        }
    };

    loadA(0); loadB(0); storeS(0);
    __syncthreads();

    for (int c = 0; c < NC; c++) {
        const int cur = c & 1;
        const bool more = (c + 1) < NC;
        if (more) { loadA(c + 1); loadB(c + 1); }
        compute(cur);
        if (more) { storeS(cur ^ 1); __syncthreads(); }
    }

    // ---- fused epilogue ----
    float* msg_new = nullptr;
    if (EPI == 1) msg_new = srcIsMsg0 ? g_msg1 : g_msg0;
    #pragma unroll
    for (int mt = 0; mt < 4; mt++) {
        const int rbase = m0 + warpM * 64 + mt * 16 + r8;
        #pragma unroll
        for (int half = 0; half < 2; half++) {
            const int r = rbase + half * 8;
            if (r >= M) continue;
            const size_t ro = (size_t)r * HID;
            #pragma unroll
            for (int nt = 0; nt < 4; nt++) {
                const int c0 = n0 + warpN * 32 + nt * 8 + q * 2;
                if (c0 >= HID) continue;
                const float v0 = acc[mt][nt][half * 2 + 0];
                const float v1 = acc[mt][nt][half * 2 + 1];
                if (EPI == 0) {
                    *(float2*)&g_inp [ro + c0] = make_float2(v0, v1);
                    *(float2*)&g_msg0[ro + c0] = make_float2(fmaxf(v0, 0.f), fmaxf(v1, 0.f));
                } else if (EPI == 1) {
                    const float2 ip = *(const float2*)&g_inp[ro + c0];
                    *(float2*)&msg_new[ro + c0] =
                        make_float2(fmaxf(ip.x + v0, 0.f), fmaxf(ip.y + v1, 0.f));
                } else {
                    *(float2*)&Cout[ro + c0] =
                        make_float2(fmaxf(v0 + bias[c0], 0.f), fmaxf(v1 + bias[c0 + 1], 0.f));
                }
            }
        }
    }
}

// a_message[a] = sum_j message[a2b[a][j]]
__global__ __launch_bounds__(128)
void aggregate_kernel(const int* __restrict__ a2b, int srcIsMsg0)
{
    const float* __restrict__ msg = srcIsMsg0 ? g_msg0 : g_msg1;
    const int a = blockIdx.x;
    const int* row = a2b + (size_t)a * MAX_NB;
    const float4* p[MAX_NB];
    #pragma unroll
    for (int j = 0; j < MAX_NB; j++)
        p[j] = (const float4*)(msg + (size_t)row[j] * HID);
    float4* outp = (float4*)(g_amsg + (size_t)a * HID);
    for (int h = threadIdx.x; h < HID / 4; h += blockDim.x) {
        float4 s = p[0][h];
        #pragma unroll
        for (int j = 1; j < MAX_NB; j++) {
            const float4 v = p[j][h];
            s.x += v.x; s.y += v.y; s.z += v.z; s.w += v.w;
        }
        outp[h] = s;
    }
}

extern "C" void kernel_launch(void* const* d_in, const int* in_sizes, int n_in,
                              void* d_out, int out_size)
{
    const float* f_atoms = (const float*)d_in[0];
    const float* f_bonds = (const float*)d_in[1];
    const int*   a2b     = (const int*)  d_in[2];
    const int*   b2a     = (const int*)  d_in[3];
    const int*   b2revb  = (const int*)  d_in[4];
    const float* W_i     = (const float*)d_in[5];
    const float* W_h     = (const float*)d_in[6];
    const float* W_o     = (const float*)d_in[7];
    const float* b_o     = (const float*)d_in[8];
    float* out = (float*)d_out;

    pack_weights<0><<<(HID * NC_I + 255) / 256, 256>>>(W_i);
    pack_weights<1><<<(HID * NC_H + 255) / 256, 256>>>(W_h);
    pack_weights<2><<<(HID * NC_O + 255) / 256, 256>>>(W_o);

    const dim3 blk(256);
    const dim3 grid_b((HID + 127) / 128, (N_BONDS + 127) / 128); // 5 x 782
    const dim3 grid_a((HID + 127) / 128, (N_ATOMS + 127) / 128); // 5 x 391

    gemm_bf16x3<0, 0><<<grid_b, blk>>>(f_bonds, nullptr, nullptr, nullptr, nullptr,
                                       N_BONDS, 0);

    int src = 1;  // message currently in g_msg0
    for (int it = 0; it < 5; it++) {
        aggregate_kernel<<<N_ATOMS, 128>>>(a2b, src);
        gemm_bf16x3<1, 1><<<grid_b, blk>>>(nullptr, b2a, b2revb, nullptr, nullptr,
                                           N_BONDS, src);
        src ^= 1;
    }

    aggregate_kernel<<<N_ATOMS, 128>>>(a2b, src);
    gemm_bf16x3<2, 2><<<grid_a, blk>>>(f_atoms, nullptr, nullptr, b_o, out,
                                       N_ATOMS, 0);
}